// round 1
// baseline (speedup 1.0000x reference)
#include <cuda_runtime.h>
#include <math.h>

// ---------------- problem-size caps (fixed for this instance) ----------------
#define MAX_B   32768
#define MAX_NS  1000000
#define MAX_NC  1024
#define NTAB    31

// ---------------- scratch (device globals; no allocations) ----------------
__device__ float g_sum_ins[MAX_NS];
__device__ int   g_cnt_ins[MAX_NS];
__device__ float g_sum_cls[MAX_NC];
__device__ int   g_cnt_cls[MAX_NC];
__device__ float g_loss[MAX_B];
__device__ float g_acc;

// conf table (CONF from reference)
__device__ const float g_conf[NTAB] = {
    0.9991138577461243f, 0.8724386692047119f, 0.8048540353775024f, 0.7398145198822021f,
    0.6715637445449829f, 0.5973713397979736f, 0.5154045820236206f, 0.42423248291015625f,
    0.3226756751537323f, 0.20976418256759644f, 0.08473344892263412f, -0.05296758562326431f,
    -0.2036692053079605f, -0.3674810528755188f, -0.5443023443222046f, -0.7338425517082214f,
    -0.9356498718261719f, -1.149145483970642f, -1.3736592531204224f, -1.6084641218185425f,
    -1.8528070449829102f, -2.1059343814849854f, -2.367111921310425f, -2.6356399059295654f,
    -2.910861015319824f, -3.1921679973602295f, -3.479003667831421f, -3.770861864089966f,
    -4.067285060882568f, -4.367861747741699f, -4.67222261428833f
};

// ---------------- helpers ----------------
__device__ __forceinline__ float warpMax(float v) {
#pragma unroll
    for (int o = 16; o > 0; o >>= 1) v = fmaxf(v, __shfl_xor_sync(0xffffffffu, v, o));
    return v;
}
__device__ __forceinline__ float warpSum(float v) {
#pragma unroll
    for (int o = 16; o > 0; o >>= 1) v += __shfl_xor_sync(0xffffffffu, v, o);
    return v;
}

// 1D border-clamped linear interp into CONF table (log-spaced grid), then exp.
__device__ __forceinline__ float optimal_conf(float l) {
    // endpoints of log(LOSS_DIV_WD + 0.750256) in f32, computed from exact literals
    const float lg0  = logf(-0.7357585932962737f + 0.750256f);
    const float lg30 = logf(999.249744f + 0.750256f);
    const float step = (lg30 - lg0) * 0.5f;     // step*(N-1)/2
    const float off  = lg0 + step;

    float ln = (logf(l + 0.750256f) - off) / step;
    if (isnan(ln)) ln = -1.0f;                  // log of negative -> left border
    float ix = (ln + 1.0f) * 0.5f * (float)(NTAB - 1);
    ix = fminf(fmaxf(ix, 0.0f), (float)(NTAB - 1));
    float i0f  = floorf(ix);
    float frac = ix - i0f;
    int   i0 = (int)i0f;
    int   i1 = min(i0 + 1, NTAB - 1);
    float r = g_conf[i0] * (1.0f - frac) + g_conf[i1] * frac;
    return expf(r);
}

__device__ __forceinline__ float smooth_val(float sum, int cnt, float mem, float smoothing) {
    // caller guarantees cnt > 0 (this sample contributed to the bin)
    float fc = (float)cnt;
    float mean = sum / fc;
    float alpha = powf(smoothing, fc);
    return alpha * mem + (1.0f - alpha) * mean;
}

// ---------------- kernel 1: zero the bins that will be touched ----------------
__global__ void zero_kernel(const int* __restrict__ indices, int B, int ncls) {
    int t = blockIdx.x * blockDim.x + threadIdx.x;
    if (t < B) {
        int i = indices[t];
        g_sum_ins[i] = 0.0f;
        g_cnt_ins[i] = 0;
    }
    if (t < ncls) {
        g_sum_cls[t] = 0.0f;
        g_cnt_cls[t] = 0;
    }
    if (t == 0) g_acc = 0.0f;
}

// ---------------- kernel 2: per-row CE loss + scatter into bins ----------------
__global__ void loss_kernel(const float* __restrict__ preds,
                            const int*   __restrict__ labels,
                            const int*   __restrict__ indices,
                            int ncls) {
    extern __shared__ float srow[];
    __shared__ float sred[32];

    const int b   = blockIdx.x;
    const int tid = threadIdx.x;
    const int nt  = blockDim.x;
    const float* row = preds + (long long)b * ncls;

    // stage row in shared memory (vectorized when possible)
    if ((ncls & 3) == 0) {
        const float4* row4  = (const float4*)row;
        float4*       srow4 = (float4*)srow;
        int nvec = ncls >> 2;
        for (int j = tid; j < nvec; j += nt) srow4[j] = row4[j];
    } else {
        for (int j = tid; j < ncls; j += nt) srow[j] = row[j];
    }
    __syncthreads();

    // block max
    float m = -INFINITY;
    for (int j = tid; j < ncls; j += nt) m = fmaxf(m, srow[j]);
    m = warpMax(m);
    const int wid = tid >> 5, lane = tid & 31, nw = nt >> 5;
    if (lane == 0) sred[wid] = m;
    __syncthreads();
    if (wid == 0) {
        float v = (lane < nw) ? sred[lane] : -INFINITY;
        v = warpMax(v);
        if (lane == 0) sred[0] = v;
    }
    __syncthreads();
    m = sred[0];
    __syncthreads();

    // block sum of exp
    float s = 0.0f;
    for (int j = tid; j < ncls; j += nt) s += expf(srow[j] - m);
    s = warpSum(s);
    if (lane == 0) sred[wid] = s;
    __syncthreads();

    if (tid == 0) {
        float tot = 0.0f;
        for (int i = 0; i < nw; i++) tot += sred[i];
        int lab = labels[b];
        float lb = logf(tot) + m - srow[lab];
        g_loss[b] = lb;
        int idx = indices[b];
        atomicAdd(&g_sum_ins[idx], lb);
        atomicAdd(&g_cnt_ins[idx], 1);
        atomicAdd(&g_sum_cls[lab], lb);
        atomicAdd(&g_cnt_cls[lab], 1);
    }
}

// ---------------- kernel 3: smooth + conf + weighted sum ----------------
__global__ void finalize_kernel(const float* __restrict__ mem_ins,
                                const float* __restrict__ mem_cls,
                                const int*   __restrict__ labels,
                                const int*   __restrict__ indices,
                                int B) {
    int b = blockIdx.x * blockDim.x + threadIdx.x;
    float contrib = 0.0f;
    if (b < B) {
        float lb  = g_loss[b];
        int   idx = indices[b];
        int   lab = labels[b];
        float sl_ins = smooth_val(g_sum_ins[idx], g_cnt_ins[idx], mem_ins[idx], 0.9f);
        float sl_cls = smooth_val(g_sum_cls[lab], g_cnt_cls[lab], mem_cls[lab], 0.9f);
        contrib = lb * optimal_conf(sl_ins) * optimal_conf(sl_cls);
    }
    // block reduce then one atomic per block
    __shared__ float sred[32];
    contrib = warpSum(contrib);
    int wid = threadIdx.x >> 5, lane = threadIdx.x & 31, nw = blockDim.x >> 5;
    if (lane == 0) sred[wid] = contrib;
    __syncthreads();
    if (wid == 0) {
        float v = (lane < nw) ? sred[lane] : 0.0f;
        v = warpSum(v);
        if (lane == 0) atomicAdd(&g_acc, v);
    }
}

// ---------------- kernel 4: write scalar output ----------------
__global__ void write_out_kernel(float* __restrict__ out, int B) {
    out[0] = g_acc / (float)B;
}

// ---------------- launch ----------------
extern "C" void kernel_launch(void* const* d_in, const int* in_sizes, int n_in,
                              void* d_out, int out_size) {
    const float* preds   = (const float*)d_in[0];
    const float* mem_ins = (const float*)d_in[1];
    const float* mem_cls = (const float*)d_in[2];
    const int*   labels  = (const int*)d_in[3];
    const int*   indices = (const int*)d_in[4];

    const int B    = in_sizes[3];                 // labels count
    const int ncls = in_sizes[0] / B;             // preds is [B, ncls]

    const int T = 256;
    int zgrid = ((B > ncls ? B : ncls) + T - 1) / T;
    zero_kernel<<<zgrid, T>>>(indices, B, ncls);

    size_t smem = (size_t)ncls * sizeof(float);
    loss_kernel<<<B, T, smem>>>(preds, labels, indices, ncls);

    finalize_kernel<<<(B + T - 1) / T, T>>>(mem_ins, mem_cls, labels, indices, B);

    write_out_kernel<<<1, 1>>>((float*)d_out, B);
}

// round 2
// speedup vs baseline: 2.6007x; 2.6007x over previous
#include <cuda_runtime.h>
#include <math.h>

// ---------------- problem-size caps (fixed for this instance) ----------------
#define MAX_B   32768
#define MAX_NS  1000000
#define MAX_NC  1024
#define NTAB    31

// ---------------- scratch (device globals; no allocations) ----------------
__device__ float2   g_ins[MAX_NS];   // (sum, count) per instance bin
__device__ float2   g_cls[MAX_NC];   // (sum, count) per class bin
__device__ float    g_loss[MAX_B];
__device__ float    g_acc;
__device__ unsigned g_done;

// conf table (CONF from reference)
__device__ const float g_conf[NTAB] = {
    0.9991138577461243f, 0.8724386692047119f, 0.8048540353775024f, 0.7398145198822021f,
    0.6715637445449829f, 0.5973713397979736f, 0.5154045820236206f, 0.42423248291015625f,
    0.3226756751537323f, 0.20976418256759644f, 0.08473344892263412f, -0.05296758562326431f,
    -0.2036692053079605f, -0.3674810528755188f, -0.5443023443222046f, -0.7338425517082214f,
    -0.9356498718261719f, -1.149145483970642f, -1.3736592531204224f, -1.6084641218185425f,
    -1.8528070449829102f, -2.1059343814849854f, -2.367111921310425f, -2.6356399059295654f,
    -2.910861015319824f, -3.1921679973602295f, -3.479003667831421f, -3.770861864089966f,
    -4.067285060882568f, -4.367861747741699f, -4.67222261428833f
};

// ---------------- helpers ----------------
__device__ __forceinline__ float warpMax(float v) {
#pragma unroll
    for (int o = 16; o > 0; o >>= 1) v = fmaxf(v, __shfl_xor_sync(0xffffffffu, v, o));
    return v;
}
__device__ __forceinline__ float warpSum(float v) {
#pragma unroll
    for (int o = 16; o > 0; o >>= 1) v += __shfl_xor_sync(0xffffffffu, v, o);
    return v;
}

__device__ __forceinline__ float optimal_conf(float l) {
    const float lg0  = logf(-0.7357585932962737f + 0.750256f);
    const float lg30 = logf(999.249744f + 0.750256f);
    const float step = (lg30 - lg0) * 0.5f;     // step*(N-1)/2
    const float off  = lg0 + step;

    float ln = (logf(l + 0.750256f) - off) / step;
    if (isnan(ln)) ln = -1.0f;                  // log of negative -> left border
    float ix = (ln + 1.0f) * 0.5f * (float)(NTAB - 1);
    ix = fminf(fmaxf(ix, 0.0f), (float)(NTAB - 1));
    float i0f  = floorf(ix);
    float frac = ix - i0f;
    int   i0 = (int)i0f;
    int   i1 = min(i0 + 1, NTAB - 1);
    float r = g_conf[i0] * (1.0f - frac) + g_conf[i1] * frac;
    return expf(r);
}

__device__ __forceinline__ float smooth_val(float2 bin, float mem, float smoothing) {
    float fc = bin.y;                     // count > 0 guaranteed for this sample's bin
    float mean = bin.x / fc;
    float alpha = powf(smoothing, fc);
    return alpha * mem + (1.0f - alpha) * mean;
}

// ---------------- kernel 1: zero touched bins + scalars ----------------
__global__ void zero_kernel(const int* __restrict__ indices, int B, int ncls) {
    int t = blockIdx.x * blockDim.x + threadIdx.x;
    if (t < B) {
        g_ins[indices[t]] = make_float2(0.0f, 0.0f);
    }
    if (t < ncls) {
        g_cls[t] = make_float2(0.0f, 0.0f);
    }
    if (t == 0) { g_acc = 0.0f; g_done = 0u; }
}

// ---------------- kernel 2: warp-per-row CE loss + scatter ----------------
// Requires ncls % 4 == 0 and ncls <= 1024 (instance: 1000).
__global__ __launch_bounds__(256) void loss_warp_kernel(
        const float* __restrict__ preds,
        const int*   __restrict__ labels,
        const int*   __restrict__ indices,
        int ncls, int B) {
    const int warp = (blockIdx.x * blockDim.x + threadIdx.x) >> 5;
    const int lane = threadIdx.x & 31;
    if (warp >= B) return;

    const int nvec = ncls >> 2;
    const float4* row = (const float4*)(preds + (size_t)warp * ncls);

    // front-batched register-resident load of this row (MLP_p1 = 8)
    float4 v[8];
#pragma unroll
    for (int it = 0; it < 8; it++) {
        int j = lane + (it << 5);
        v[it] = (j < nvec) ? row[j]
                           : make_float4(-INFINITY, -INFINITY, -INFINITY, -INFINITY);
    }

    // max
    float m = -INFINITY;
#pragma unroll
    for (int it = 0; it < 8; it++)
        m = fmaxf(m, fmaxf(fmaxf(v[it].x, v[it].y), fmaxf(v[it].z, v[it].w)));
    m = warpMax(m);

    // sum of exp via exp2 (exp2f(-inf) == 0 handles padding lanes)
    const float L2E = 1.4426950408889634f;
    float s = 0.0f;
#pragma unroll
    for (int it = 0; it < 8; it++) {
        s += exp2f((v[it].x - m) * L2E);
        s += exp2f((v[it].y - m) * L2E);
        s += exp2f((v[it].z - m) * L2E);
        s += exp2f((v[it].w - m) * L2E);
    }
    s = warpSum(s);

    // fetch preds[warp][lab] from the lane that owns it
    int lab = labels[warp];
    int vecidx   = lab >> 2;
    int src_lane = vecidx & 31;
    int itw      = vecidx >> 5;
    int comp     = lab & 3;
    float cand = 0.0f;
#pragma unroll
    for (int it = 0; it < 8; it++) {
        if (it == itw) {
            float c = (comp == 0) ? v[it].x : (comp == 1) ? v[it].y
                    : (comp == 2) ? v[it].z : v[it].w;
            cand = c;
        }
    }
    float plab = __shfl_sync(0xffffffffu, cand, src_lane);

    if (lane == 0) {
        float lb = logf(s) + m - plab;
        g_loss[warp] = lb;
        int idx = indices[warp];
        atomicAdd(&g_ins[idx].x, lb);
        atomicAdd(&g_ins[idx].y, 1.0f);
        atomicAdd(&g_cls[lab].x, lb);
        atomicAdd(&g_cls[lab].y, 1.0f);
    }
}

// ---------------- fallback: block-per-row (generic ncls) ----------------
__global__ void loss_block_kernel(const float* __restrict__ preds,
                                  const int*   __restrict__ labels,
                                  const int*   __restrict__ indices,
                                  int ncls) {
    extern __shared__ float srow[];
    __shared__ float sred[32];
    const int b = blockIdx.x, tid = threadIdx.x, nt = blockDim.x;
    const float* row = preds + (size_t)b * ncls;
    for (int j = tid; j < ncls; j += nt) srow[j] = row[j];
    __syncthreads();
    float m = -INFINITY;
    for (int j = tid; j < ncls; j += nt) m = fmaxf(m, srow[j]);
    m = warpMax(m);
    const int wid = tid >> 5, lane = tid & 31, nw = nt >> 5;
    if (lane == 0) sred[wid] = m;
    __syncthreads();
    if (wid == 0) { float t = (lane < nw) ? sred[lane] : -INFINITY; t = warpMax(t); if (lane == 0) sred[0] = t; }
    __syncthreads();
    m = sred[0];
    __syncthreads();
    float s = 0.0f;
    for (int j = tid; j < ncls; j += nt) s += expf(srow[j] - m);
    s = warpSum(s);
    if (lane == 0) sred[wid] = s;
    __syncthreads();
    if (tid == 0) {
        float tot = 0.0f;
        for (int i = 0; i < nw; i++) tot += sred[i];
        int lab = labels[b];
        float lb = logf(tot) + m - srow[lab];
        g_loss[b] = lb;
        int idx = indices[b];
        atomicAdd(&g_ins[idx].x, lb);
        atomicAdd(&g_ins[idx].y, 1.0f);
        atomicAdd(&g_cls[lab].x, lb);
        atomicAdd(&g_cls[lab].y, 1.0f);
    }
}

// ---------------- kernel 3: smooth + conf + weighted mean + write ----------------
__global__ void finalize_kernel(const float* __restrict__ mem_ins,
                                const float* __restrict__ mem_cls,
                                const int*   __restrict__ labels,
                                const int*   __restrict__ indices,
                                int B, float* __restrict__ out) {
    int b = blockIdx.x * blockDim.x + threadIdx.x;
    float contrib = 0.0f;
    if (b < B) {
        float lb  = g_loss[b];
        int   idx = indices[b];
        int   lab = labels[b];
        float sl_ins = smooth_val(g_ins[idx], mem_ins[idx], 0.9f);
        float sl_cls = smooth_val(g_cls[lab], mem_cls[lab], 0.9f);
        contrib = lb * optimal_conf(sl_ins) * optimal_conf(sl_cls);
    }
    __shared__ float sred[32];
    contrib = warpSum(contrib);
    int wid = threadIdx.x >> 5, lane = threadIdx.x & 31, nw = blockDim.x >> 5;
    if (lane == 0) sred[wid] = contrib;
    __syncthreads();
    if (wid == 0) {
        float v = (lane < nw) ? sred[lane] : 0.0f;
        v = warpSum(v);
        if (lane == 0) {
            atomicAdd(&g_acc, v);
            __threadfence();
            unsigned done = atomicAdd(&g_done, 1u);
            if (done == gridDim.x - 1) {
                float a = atomicAdd(&g_acc, 0.0f);   // coherent read
                out[0] = a / (float)B;
            }
        }
    }
}

// ---------------- launch ----------------
extern "C" void kernel_launch(void* const* d_in, const int* in_sizes, int n_in,
                              void* d_out, int out_size) {
    const float* preds   = (const float*)d_in[0];
    const float* mem_ins = (const float*)d_in[1];
    const float* mem_cls = (const float*)d_in[2];
    const int*   labels  = (const int*)d_in[3];
    const int*   indices = (const int*)d_in[4];

    const int B    = in_sizes[3];
    const int ncls = in_sizes[0] / B;

    const int T = 256;
    int zgrid = ((B > ncls ? B : ncls) + T - 1) / T;
    zero_kernel<<<zgrid, T>>>(indices, B, ncls);

    if ((ncls & 3) == 0 && ncls <= 1024) {
        int warps_per_block = T / 32;
        int grid = (B + warps_per_block - 1) / warps_per_block;
        loss_warp_kernel<<<grid, T>>>(preds, labels, indices, ncls, B);
    } else {
        size_t smem = (size_t)ncls * sizeof(float);
        loss_block_kernel<<<B, T, smem>>>(preds, labels, indices, ncls);
    }

    finalize_kernel<<<(B + T - 1) / T, T>>>(mem_ins, mem_cls, labels, indices, B,
                                            (float*)d_out);
}